// round 6
// baseline (speedup 1.0000x reference)
#include <cuda_runtime.h>

// TemporalSpike RLeaky recurrence — R5: 4 rows per warp for 512B DRAM granules.
//   rec = spk_prev @ W^T + b_lin  (binary spk -> warp-uniform ballot mask ->
//                                  8 nibble lookups in 16KB smem LUT, per row)
//   mem = 0.9*mem + x_t + rec - spk ;  spk = (mem > 1)
// x (16,128,512,32); W (32,32); b (32). Out: spikes then mems, concatenated.
//
// Each warp owns 4 consecutive n-rows (lane = feature). Per step it loads
// 4 consecutive 128B lines (512B contiguous) and stores 2x512B contiguous,
// with 4 independent recurrence chains interleaved for latency tolerance.

#define BB 16
#define TT 128
#define NN 512
#define FF 32
#define RPW 4                    // rows (n) per warp
#define WPB 4                    // warps per block
#define NWARP (BB * NN / RPW)    // 2048
#define TSTRIDE (NN * FF)        // 16384 floats between consecutive t

#define TAB_ELEMS (8 * 16 * 32)  // nibble LUT, bias folded into p==0

__global__ __launch_bounds__(WPB * 32)
void temporal_spike_kernel(const float* __restrict__ x,
                           const float* __restrict__ W,
                           const float* __restrict__ b_lin,
                           float* __restrict__ out)
{
    __shared__ float tab[TAB_ELEMS];   // 16 KB

    const int lane = threadIdx.x & 31;

    // Build LUT: tab[p*512 + v*32 + g] = (p==0 ? bias[g] : 0) + sum_j W[g][4p+j]*bit_j(v)
    for (int e = threadIdx.x; e < TAB_ELEMS; e += WPB * 32) {
        const int g = e & 31;
        const int v = (e >> 5) & 15;
        const int p = e >> 9;
        float s = (p == 0) ? b_lin[g] : 0.0f;
        const float* wr = W + g * FF + 4 * p;
        #pragma unroll
        for (int j = 0; j < 4; j++)
            if (v & (1 << j)) s += wr[j];
        tab[e] = s;
    }
    __syncthreads();

    const int wi = blockIdx.x * WPB + (threadIdx.x >> 5);  // 0..2047
    const int b  = wi >> 7;                // 128 n-chunks per b
    const int n0 = (wi & 127) * RPW;       // 4 consecutive n rows

    const int base = (b * TT * NN + n0) * FF + lane;
    const float* xp = x + base;
    float* sp = out + base;                              // spikes
    float* mp = sp + (size_t)BB * TT * NN * FF;          // mems

    float    mem[RPW]  = {0.f, 0.f, 0.f, 0.f};
    float    spk[RPW]  = {0.f, 0.f, 0.f, 0.f};
    unsigned mask[RPW] = {0u, 0u, 0u, 0u};

    // Prefetch pipeline, depth 4, 4 consecutive lines per stage.
    float xbuf[4][RPW];
    #pragma unroll
    for (int i = 0; i < 4; i++)
        #pragma unroll
        for (int r = 0; r < RPW; r++)
            xbuf[i][r] = xp[i * TSTRIDE + r * FF];

    #pragma unroll 4
    for (int t = 0; t < TT; t++) {
        float xv[RPW];
        #pragma unroll
        for (int r = 0; r < RPW; r++) xv[r] = xbuf[t & 3][r];
        if (t + 4 < TT) {
            #pragma unroll
            for (int r = 0; r < RPW; r++)
                xbuf[t & 3][r] = xp[(t + 4) * TSTRIDE + r * FF];
        }

        #pragma unroll
        for (int r = 0; r < RPW; r++) {
            const unsigned m = mask[r];
            float a0, a1, a2, a3;
            a0 = tab[0 * 512 + ((m      ) & 15) * 32 + lane];
            a1 = tab[1 * 512 + ((m >>  4) & 15) * 32 + lane];
            a2 = tab[2 * 512 + ((m >>  8) & 15) * 32 + lane];
            a3 = tab[3 * 512 + ((m >> 12) & 15) * 32 + lane];
            a0 += tab[4 * 512 + ((m >> 16) & 15) * 32 + lane];
            a1 += tab[5 * 512 + ((m >> 20) & 15) * 32 + lane];
            a2 += tab[6 * 512 + ((m >> 24) & 15) * 32 + lane];
            a3 += tab[7 * 512 + ((m >> 28)     ) * 32 + lane];
            const float rec = (a0 + a1) + (a2 + a3);

            mem[r] = fmaf(0.9f, mem[r], xv[r] + rec - spk[r]);
            const bool fire = (mem[r] > 1.0f);
            spk[r] = fire ? 1.0f : 0.0f;
            mask[r] = __ballot_sync(0xffffffffu, fire);

            sp[t * TSTRIDE + r * FF] = spk[r];
            mp[t * TSTRIDE + r * FF] = mem[r];
        }
    }
}

extern "C" void kernel_launch(void* const* d_in, const int* in_sizes, int n_in,
                              void* d_out, int out_size)
{
    const float* x     = (const float*)d_in[0];
    const float* W     = (const float*)d_in[1];
    const float* b_lin = (const float*)d_in[2];
    float* out = (float*)d_out;

    dim3 grid(NWARP / WPB);    // 512
    dim3 block(WPB * 32);      // 128
    temporal_spike_kernel<<<grid, block>>>(x, W, b_lin, out);
}

// round 8
// speedup vs baseline: 1.4093x; 1.4093x over previous
#include <cuda_runtime.h>

// TemporalSpike RLeaky recurrence — nibble-LUT + full-occupancy carveout.
//   rec = spk_prev @ W^T + b_lin  (binary spk -> warp-uniform ballot mask ->
//                                  8 nibble lookups in 16KB smem LUT)
//   mem = 0.9*mem + x_t + rec - spk ;  spk = (mem > 1)
// x (16,128,512,32); W (32,32); b (32). Out: spikes then mems, concatenated.
//
// R6: identical inner loop to the 98us r4 kernel; the one change is the
// shared-memory carveout hint so 8 blocks x 16KB fit per SM -> 64 warps/SM.

#define BB 16
#define TT 128
#define NN 512
#define FF 32
#define ROWS (BB * NN)          // 8192 independent recurrences
#define WPB 8                   // warps per block
#define TSTRIDE (NN * FF)       // 16384 floats between consecutive t

#define TAB_ELEMS (8 * 16 * 32) // nibble LUT, bias folded into p==0

__global__ __launch_bounds__(WPB * 32, 8)
void temporal_spike_kernel(const float* __restrict__ x,
                           const float* __restrict__ W,
                           const float* __restrict__ b_lin,
                           float* __restrict__ out)
{
    __shared__ float tab[TAB_ELEMS];   // 16 KB

    const int lane = threadIdx.x & 31;

    // Build LUT: tab[p*512 + v*32 + g] = (p==0 ? bias[g] : 0) + sum_j bit_j(v)*W[g][4p+j]
    for (int e = threadIdx.x; e < TAB_ELEMS; e += WPB * 32) {
        const int g = e & 31;
        const int v = (e >> 5) & 15;
        const int p = e >> 9;
        float s = (p == 0) ? b_lin[g] : 0.0f;
        const float* wr = W + g * FF + 4 * p;
        #pragma unroll
        for (int j = 0; j < 4; j++)
            if (v & (1 << j)) s += wr[j];
        tab[e] = s;
    }
    __syncthreads();

    const int warp = blockIdx.x * WPB + (threadIdx.x >> 5);
    const int b = warp >> 9;        // / NN
    const int n = warp & (NN - 1);

    const int base = (b * TT * NN + n) * FF + lane;   // t=0 element for this lane
    const float* xp = x + base;
    float* sp = out + base;                            // spikes
    float* mp = sp + (size_t)BB * TT * NN * FF;        // mems (second half)

    float mem = 0.0f;
    float spk = 0.0f;
    unsigned mask = 0u;

    // Prefetch pipeline for x (independent of the recurrence), depth 4.
    float xbuf[4];
    #pragma unroll
    for (int i = 0; i < 4; i++) xbuf[i] = xp[i * TSTRIDE];

    #pragma unroll 4
    for (int t = 0; t < TT; t++) {
        const float xv = xbuf[t & 3];
        if (t + 4 < TT) xbuf[t & 3] = xp[(t + 4) * TSTRIDE];

        // rec = sum of 8 nibble-table entries (mask warp-uniform -> no conflicts).
        float r0, r1, r2, r3;
        r0 = tab[0 * 512 + ((mask      ) & 15) * 32 + lane];
        r1 = tab[1 * 512 + ((mask >>  4) & 15) * 32 + lane];
        r2 = tab[2 * 512 + ((mask >>  8) & 15) * 32 + lane];
        r3 = tab[3 * 512 + ((mask >> 12) & 15) * 32 + lane];
        r0 += tab[4 * 512 + ((mask >> 16) & 15) * 32 + lane];
        r1 += tab[5 * 512 + ((mask >> 20) & 15) * 32 + lane];
        r2 += tab[6 * 512 + ((mask >> 24) & 15) * 32 + lane];
        r3 += tab[7 * 512 + ((mask >> 28)     ) * 32 + lane];
        const float rec = (r0 + r1) + (r2 + r3);

        mem = fmaf(0.9f, mem, xv + rec - spk);   // THRESH=1 -> subtract spk
        const bool fire = (mem > 1.0f);
        spk = fire ? 1.0f : 0.0f;
        mask = __ballot_sync(0xffffffffu, fire);

        sp[t * TSTRIDE] = spk;
        mp[t * TSTRIDE] = mem;
    }
}

extern "C" void kernel_launch(void* const* d_in, const int* in_sizes, int n_in,
                              void* d_out, int out_size)
{
    const float* x     = (const float*)d_in[0];
    const float* W     = (const float*)d_in[1];
    const float* b_lin = (const float*)d_in[2];
    float* out = (float*)d_out;

    // One-time-effective, idempotent, capture-safe: raise shared carveout so
    // 8 blocks x 16KB static smem fit per SM (default carveout capped us at 6).
    cudaFuncSetAttribute(temporal_spike_kernel,
                         cudaFuncAttributePreferredSharedMemoryCarveout, 100);

    dim3 grid(ROWS / WPB);     // 1024
    dim3 block(WPB * 32);      // 256
    temporal_spike_kernel<<<grid, block>>>(x, W, b_lin, out);
}

// round 9
// speedup vs baseline: 1.5413x; 1.0937x over previous
#include <cuda_runtime.h>
#include <cstdint>

// TemporalSpike RLeaky recurrence — R8: tile-synchronized burst memory.
//   rec = spk_prev @ W^T + b_lin  (binary spk -> warp-uniform ballot mask ->
//                                  8 nibble lookups in 16KB smem LUT)
//   mem = 0.9*mem + x_t + rec - spk ;  spk = (mem > 1)
// x (16,128,512,32); W (32,32); b (32). Out: spikes then mems, concatenated.
//
// Block = 8 warps = 8 consecutive n-rows. t processed in tiles of 4 steps:
//   - x staged via cp.async.cg (16B/thread), double-buffered: per tile the
//     block issues 4 x 1KB contiguous bursts, fully overlapped with compute.
//   - per-tile __syncthreads keeps the 8 warps' 128B stores clustered into
//     1KB runs; stores use st.global.cs (streaming, write-once data).

#define BB 16
#define TT 128
#define NN 512
#define FF 32
#define ROWS (BB * NN)
#define WPB 8
#define TSTRIDE (NN * FF)        // 16384 floats between t-slices
#define TILE 4
#define NTILE (TT / TILE)        // 32
#define TAB_ELEMS (8 * 16 * 32)  // nibble LUT, bias folded into p==0
#define XS_TILE (TILE * WPB * FF)  // 1024 floats = 4KB per buffer

__device__ __forceinline__ void cp_async16(uint32_t saddr, const void* gaddr) {
    asm volatile("cp.async.cg.shared.global [%0], [%1], 16;\n"
                 :: "r"(saddr), "l"(gaddr) : "memory");
}
#define CP_COMMIT() asm volatile("cp.async.commit_group;\n" ::: "memory")
#define CP_WAIT1()  asm volatile("cp.async.wait_group 1;\n" ::: "memory")
#define CP_WAIT0()  asm volatile("cp.async.wait_group 0;\n" ::: "memory")

__global__ __launch_bounds__(WPB * 32, 8)
void temporal_spike_kernel(const float* __restrict__ x,
                           const float* __restrict__ W,
                           const float* __restrict__ b_lin,
                           float* __restrict__ out)
{
    __shared__ float tab[TAB_ELEMS];        // 16 KB
    __shared__ float xs[2][XS_TILE];        // 8 KB staging, double-buffered

    const int tid  = threadIdx.x;
    const int lane = tid & 31;
    const int w    = tid >> 5;

    // Build LUT: tab[p*512 + v*32 + g] = (p==0 ? bias[g] : 0) + sum_j bit_j(v)*W[g][4p+j]
    for (int e = tid; e < TAB_ELEMS; e += WPB * 32) {
        const int g = e & 31;
        const int v = (e >> 5) & 15;
        const int p = e >> 9;
        float s = (p == 0) ? b_lin[g] : 0.0f;
        const float* wr = W + g * FF + 4 * p;
        #pragma unroll
        for (int j = 0; j < 4; j++)
            if (v & (1 << j)) s += wr[j];
        tab[e] = s;
    }

    const int blk = blockIdx.x;
    const int b   = blk >> 6;               // 64 blocks per batch (512 rows / 8)
    const int n0  = (blk & 63) * WPB;       // 8 consecutive rows
    const size_t base_blk = ((size_t)b * TT * NN + n0) * FF;

    // Staging role: thread -> (t-slice within tile, 16B chunk within 1KB row-group)
    const int ti = tid >> 6;                // 0..3
    const int q  = tid & 63;                // 0..63 (x16B = 1KB)
    const float* gsrc = x + base_blk + (size_t)ti * TSTRIDE + q * 4;
    uint32_t sb0 = (uint32_t)__cvta_generic_to_shared(&xs[0][0]) + (ti * (WPB * FF) + q * 4) * 4;
    uint32_t sb1 = sb0 + XS_TILE * 4;

    // Prologue: tile 0 into buffer 0.
    cp_async16(sb0, gsrc);
    CP_COMMIT();

    // Compute-side pointers: warp w owns row n0+w, lane = feature.
    float* sp = out + base_blk + w * FF + lane;              // spikes
    float* mp = sp + (size_t)BB * TT * NN * FF;              // mems

    float mem = 0.0f, spk = 0.0f;
    unsigned mask = 0u;
    const float* xv = &xs[0][0] + w * FF + lane;             // + buf*XS_TILE + ti*256

    for (int k = 0; k < NTILE; k++) {
        // Issue next tile, then wait for current one.
        if (k + 1 < NTILE) {
            cp_async16((k & 1) ? sb0 : sb1,
                       gsrc + (size_t)(k + 1) * TILE * TSTRIDE);
            CP_COMMIT();
            CP_WAIT1();
        } else {
            CP_WAIT0();
        }
        __syncthreads();   // tile k visible to all (also covers LUT on k==0)

        const float* xt = xv + (k & 1) * XS_TILE;
        #pragma unroll
        for (int s = 0; s < TILE; s++) {
            const float xval = xt[s * (WPB * FF)];

            float r0, r1, r2, r3;
            r0 = tab[0 * 512 + ((mask      ) & 15) * 32 + lane];
            r1 = tab[1 * 512 + ((mask >>  4) & 15) * 32 + lane];
            r2 = tab[2 * 512 + ((mask >>  8) & 15) * 32 + lane];
            r3 = tab[3 * 512 + ((mask >> 12) & 15) * 32 + lane];
            r0 += tab[4 * 512 + ((mask >> 16) & 15) * 32 + lane];
            r1 += tab[5 * 512 + ((mask >> 20) & 15) * 32 + lane];
            r2 += tab[6 * 512 + ((mask >> 24) & 15) * 32 + lane];
            r3 += tab[7 * 512 + ((mask >> 28)     ) * 32 + lane];
            const float rec = (r0 + r1) + (r2 + r3);

            mem = fmaf(0.9f, mem, xval + rec - spk);    // THRESH=1
            const bool fire = (mem > 1.0f);
            spk = fire ? 1.0f : 0.0f;
            mask = __ballot_sync(0xffffffffu, fire);

            const size_t off = (size_t)(k * TILE + s) * TSTRIDE;
            __stcs(sp + off, spk);
            __stcs(mp + off, mem);
        }
        __syncthreads();   // all reads of buffer (k&1) done before it is refilled
    }
}

extern "C" void kernel_launch(void* const* d_in, const int* in_sizes, int n_in,
                              void* d_out, int out_size)
{
    const float* x     = (const float*)d_in[0];
    const float* W     = (const float*)d_in[1];
    const float* b_lin = (const float*)d_in[2];
    float* out = (float*)d_out;

    cudaFuncSetAttribute(temporal_spike_kernel,
                         cudaFuncAttributePreferredSharedMemoryCarveout, 100);

    dim3 grid(ROWS / WPB);     // 1024
    dim3 block(WPB * 32);      // 256
    temporal_spike_kernel<<<grid, block>>>(x, W, b_lin, out);
}

// round 10
// speedup vs baseline: 1.6050x; 1.0413x over previous
#include <cuda_runtime.h>
#include <cstdint>

// TemporalSpike RLeaky recurrence — R9: 4-stage cp.async pipeline.
//   rec = spk_prev @ W^T + b_lin  (binary spk -> warp-uniform ballot mask ->
//                                  8 nibble lookups in 16KB smem LUT)
//   mem = 0.9*mem + x_t + rec - spk ;  spk = (mem > 1)
// x (16,128,512,32); W (32,32); b (32). Out: spikes then mems, concatenated.
//
// Block = 8 warps = 8 consecutive n-rows. t in tiles of 4 steps; x staged via
// cp.async.cg (16B/thread) through FOUR 4KB buffers so 3 tiles (~12 steps of
// compute) are in flight ahead of consumption — covering ~1100cyc DRAM latency
// that the old double-buffer (1 tile ahead) did not.

#define BB 16
#define TT 128
#define NN 512
#define FF 32
#define ROWS (BB * NN)
#define WPB 8
#define TSTRIDE (NN * FF)          // 16384 floats between t-slices
#define TILE 4
#define NTILE (TT / TILE)          // 32
#define NSTAGE 4
#define TAB_ELEMS (8 * 16 * 32)    // nibble LUT, bias folded into p==0
#define XS_TILE (TILE * WPB * FF)  // 1024 floats = 4KB per stage

__device__ __forceinline__ void cp_async16(uint32_t saddr, const void* gaddr) {
    asm volatile("cp.async.cg.shared.global [%0], [%1], 16;\n"
                 :: "r"(saddr), "l"(gaddr) : "memory");
}
#define CP_COMMIT() asm volatile("cp.async.commit_group;\n" ::: "memory")
#define CP_WAIT(n)  asm volatile("cp.async.wait_group %0;\n" :: "n"(n) : "memory")

__global__ __launch_bounds__(WPB * 32, 6)
void temporal_spike_kernel(const float* __restrict__ x,
                           const float* __restrict__ W,
                           const float* __restrict__ b_lin,
                           float* __restrict__ out)
{
    __shared__ float tab[TAB_ELEMS];          // 16 KB
    __shared__ float xs[NSTAGE][XS_TILE];     // 16 KB staging, 4 stages

    const int tid  = threadIdx.x;
    const int lane = tid & 31;
    const int w    = tid >> 5;

    // Build LUT: tab[p*512 + v*32 + g] = (p==0 ? bias[g] : 0) + sum_j bit_j(v)*W[g][4p+j]
    for (int e = tid; e < TAB_ELEMS; e += WPB * 32) {
        const int g = e & 31;
        const int v = (e >> 5) & 15;
        const int p = e >> 9;
        float s = (p == 0) ? b_lin[g] : 0.0f;
        const float* wr = W + g * FF + 4 * p;
        #pragma unroll
        for (int j = 0; j < 4; j++)
            if (v & (1 << j)) s += wr[j];
        tab[e] = s;
    }

    const int blk = blockIdx.x;
    const int b   = blk >> 6;                 // 64 blocks per batch
    const int n0  = (blk & 63) * WPB;         // 8 consecutive rows
    const size_t base_blk = ((size_t)b * TT * NN + n0) * FF;

    // Staging role: thread -> (t-slice in tile, 16B chunk within the 1KB slice)
    const int ti = tid >> 6;                  // 0..3
    const int q  = tid & 63;                  // 0..63
    const float* gsrc = x + base_blk + (size_t)ti * TSTRIDE + q * 4;
    const uint32_t sbase = (uint32_t)__cvta_generic_to_shared(&xs[0][0])
                         + (ti * (WPB * FF) + q * 4) * 4;

    // Prologue: issue tiles 0..2 into stages 0..2 (3 groups in flight).
    #pragma unroll
    for (int k = 0; k < NSTAGE - 1; k++) {
        cp_async16(sbase + k * (XS_TILE * 4), gsrc + (size_t)k * TILE * TSTRIDE);
        CP_COMMIT();
    }

    float* sp = out + base_blk + w * FF + lane;            // spikes
    float* mp = sp + (size_t)BB * TT * NN * FF;            // mems

    float mem = 0.0f, spk = 0.0f;
    unsigned mask = 0u;
    const float* xv = &xs[0][0] + w * FF + lane;

    for (int k = 0; k < NTILE; k++) {
        // Keep 3 tiles ahead in flight; then wait for tile k.
        if (k + NSTAGE - 1 < NTILE) {
            cp_async16(sbase + ((k + NSTAGE - 1) & (NSTAGE - 1)) * (XS_TILE * 4),
                       gsrc + (size_t)(k + NSTAGE - 1) * TILE * TSTRIDE);
            CP_COMMIT();
            CP_WAIT(3);                       // 4 pending -> tile k complete
        } else if (k == NTILE - 3) {
            CP_WAIT(2);
        } else if (k == NTILE - 2) {
            CP_WAIT(1);
        } else {                              // k == NTILE-1
            CP_WAIT(0);
        }
        __syncthreads();   // tile k visible to all (also covers LUT on k==0)

        const float* xt = xv + (k & (NSTAGE - 1)) * XS_TILE;
        #pragma unroll
        for (int s = 0; s < TILE; s++) {
            const float xval = xt[s * (WPB * FF)];

            float r0, r1, r2, r3;
            r0 = tab[0 * 512 + ((mask      ) & 15) * 32 + lane];
            r1 = tab[1 * 512 + ((mask >>  4) & 15) * 32 + lane];
            r2 = tab[2 * 512 + ((mask >>  8) & 15) * 32 + lane];
            r3 = tab[3 * 512 + ((mask >> 12) & 15) * 32 + lane];
            r0 += tab[4 * 512 + ((mask >> 16) & 15) * 32 + lane];
            r1 += tab[5 * 512 + ((mask >> 20) & 15) * 32 + lane];
            r2 += tab[6 * 512 + ((mask >> 24) & 15) * 32 + lane];
            r3 += tab[7 * 512 + ((mask >> 28)     ) * 32 + lane];
            const float rec = (r0 + r1) + (r2 + r3);

            mem = fmaf(0.9f, mem, xval + rec - spk);    // THRESH=1
            const bool fire = (mem > 1.0f);
            spk = fire ? 1.0f : 0.0f;
            mask = __ballot_sync(0xffffffffu, fire);

            const size_t off = (size_t)(k * TILE + s) * TSTRIDE;
            __stcs(sp + off, spk);
            __stcs(mp + off, mem);
        }
        __syncthreads();   // release buffer (k & 3) before it is refilled
    }
}

extern "C" void kernel_launch(void* const* d_in, const int* in_sizes, int n_in,
                              void* d_out, int out_size)
{
    const float* x     = (const float*)d_in[0];
    const float* W     = (const float*)d_in[1];
    const float* b_lin = (const float*)d_in[2];
    float* out = (float*)d_out;

    cudaFuncSetAttribute(temporal_spike_kernel,
                         cudaFuncAttributePreferredSharedMemoryCarveout, 100);

    dim3 grid(ROWS / WPB);     // 1024
    dim3 block(WPB * 32);      // 256
    temporal_spike_kernel<<<grid, block>>>(x, W, b_lin, out);
}